// round 14
// baseline (speedup 1.0000x reference)
#include <cuda_runtime.h>
#include <cuda_fp16.h>
#include <stdint.h>

// Instant-NGP hash encode + MLP 32->64->64->3.
// R14: sort chain slimmed. Sorted record packed as one float4 (x,y,idx,0) ->
// single 16B random store in scatter (was 8B+4B to two arrays); hist/scatter
// process 2 points/thread (MLP=2 on the atomic chains). Encode/MLP unchanged.

#define HASHMAP_SIZE (1u << 17)
#define HMASK (HASHMAP_SIZE - 1u)
#define TILES 8
#define NBINS 16384            // 128 x 128
#define MAXN  (1 << 20)

__device__ __constant__ float SCALES[16] = {
    16.0f, 24.0f, 36.0f, 54.0f, 81.0f, 121.5f, 182.25f, 273.375f,
    410.0625f, 615.09375f, 922.640625f, 1383.9609375f,
    2075.94140625f, 3113.912109375f, 4670.8681640625f, 7006.30224609375f
};

__device__ __align__(16) float    g_enc2[16 * HASHMAP_SIZE * 2];  // [level][idx][2]
__device__ __align__(16) uint4    g_feat[MAXN * 4];               // sorted-order feats
__device__ __align__(16) float4   g_pts[MAXN];                    // (x, y, bits(idx), 0)
__device__ unsigned g_hist[NBINS];
__device__ unsigned g_binCur[NBINS];

// ---- relayout: [idx][16][2] -> [level][idx][2]; first 64 CTAs also zero hist ----
__global__ void __launch_bounds__(256)
relayout_kernel(const float* __restrict__ enc)
{
    if (blockIdx.x < 64) {
        g_hist[blockIdx.x * 256 + threadIdx.x] = 0u;
    }

    __shared__ float s[256 * 33];
    const unsigned base = blockIdx.x * 256;          // idx tile
    for (int i = threadIdx.x; i < 256 * 8; i += 256) {
        const float4 v = ((const float4*)enc)[base * 8 + i];
        const int row = i >> 3, q = i & 7;
        s[row * 33 + q * 4 + 0] = v.x;
        s[row * 33 + q * 4 + 1] = v.y;
        s[row * 33 + q * 4 + 2] = v.z;
        s[row * 33 + q * 4 + 3] = v.w;
    }
    __syncthreads();
    const int i = threadIdx.x;
    #pragma unroll
    for (int l = 0; l < 16; l++) {
        const float2 v = make_float2(s[i * 33 + 2 * l], s[i * 33 + 2 * l + 1]);
        ((float2*)g_enc2)[(size_t)l * HASHMAP_SIZE + base + i] = v;
    }
}

// ---------------- counting sort ----------------
__device__ __forceinline__ int point_bin(float px, float py) {
    int bx = (int)(px * 128.0f); bx = bx > 127 ? 127 : bx;
    int by = (int)(py * 128.0f); by = by > 127 ? 127 : by;
    return by * 128 + bx;
}

// 2 points per thread via float4 read of x
__global__ void __launch_bounds__(256)
hist_kernel(const float4* __restrict__ x2, int N)
{
    const int p2 = blockIdx.x * 256 + threadIdx.x;     // pair index
    const int gi = p2 * 2;
    if (gi >= N) return;
    const float4 v = __ldg(x2 + p2);
    atomicAdd(&g_hist[point_bin(v.x, v.y)], 1u);
    if (gi + 1 < N)
        atomicAdd(&g_hist[point_bin(v.z, v.w)], 1u);
}

// Warp-shuffle exclusive scan over 16384 bins: 1024 threads x 16 bins each.
__global__ void __launch_bounds__(1024)
scan_kernel()
{
    __shared__ unsigned warpTot[32];
    const unsigned t    = threadIdx.x;
    const unsigned lane = t & 31u;
    const unsigned wid  = t >> 5;

    unsigned loc[16];
    unsigned s = 0;
    #pragma unroll
    for (int i = 0; i < 16; i++) { loc[i] = s; s += g_hist[t * 16 + i]; }

    unsigned incl = s;
    #pragma unroll
    for (int d = 1; d < 32; d <<= 1) {
        const unsigned v = __shfl_up_sync(0xffffffffu, incl, d);
        if (lane >= (unsigned)d) incl += v;
    }
    if (lane == 31u) warpTot[wid] = incl;
    __syncthreads();

    if (wid == 0) {
        unsigned v = warpTot[lane];
        unsigned iv = v;
        #pragma unroll
        for (int d = 1; d < 32; d <<= 1) {
            const unsigned u = __shfl_up_sync(0xffffffffu, iv, d);
            if (lane >= (unsigned)d) iv += u;
        }
        warpTot[lane] = iv - v;   // exclusive
    }
    __syncthreads();

    const unsigned base = warpTot[wid] + (incl - s);
    #pragma unroll
    for (int i = 0; i < 16; i++) g_binCur[t * 16 + i] = base + loc[i];
}

// 2 points per thread; single 16B random store per point
__global__ void __launch_bounds__(256)
scatter_kernel(const float4* __restrict__ x2, int N)
{
    const int p2 = blockIdx.x * 256 + threadIdx.x;
    const int gi = p2 * 2;
    if (gi >= N) return;
    const float4 v = __ldg(x2 + p2);
    {
        const unsigned r = atomicAdd(&g_binCur[point_bin(v.x, v.y)], 1u);
        g_pts[r] = make_float4(v.x, v.y, __int_as_float(gi), 0.0f);
    }
    if (gi + 1 < N) {
        const unsigned r = atomicAdd(&g_binCur[point_bin(v.z, v.w)], 1u);
        g_pts[r] = make_float4(v.z, v.w, __int_as_float(gi + 1), 0.0f);
    }
}

// ---------------- Kernel: hash-grid encode (sorted order) ----------------
__global__ void __launch_bounds__(256)
encode_kernel(int N)
{
    const int gi = blockIdx.x * 256 + threadIdx.x;
    if (gi >= N) return;
    const float4 pr = __ldg(&g_pts[gi]);
    const float2 xi = make_float2(pr.x, pr.y);

    uint32_t fp[16];
    #pragma unroll
    for (int l = 0; l < 16; l++) {
        const float s  = SCALES[l];
        const float px = xi.x * s, py = xi.y * s;
        const float fx = floorf(px), fy = floorf(py);
        const float tx = px - fx,  ty = py - fy;
        const unsigned ix0 = (unsigned)fx, iy0 = (unsigned)fy;
        const float* lvl = g_enc2 + (size_t)l * (HASHMAP_SIZE * 2);

        float accx = 0.0f, accy = 0.0f;
        #pragma unroll
        for (int cy = 0; cy < 2; cy++) {
            const unsigned t  = (iy0 + (unsigned)cy) * 2654435761u;
            const unsigned i0 = (ix0 ^ t) & HMASK;
            const unsigned i1 = ((ix0 + 1u) ^ t) & HMASK;
            const float wy  = cy ? ty : (1.0f - ty);
            const float wx0 = (1.0f - tx) * wy;
            const float wx1 = tx * wy;

            const float4 v = __ldg((const float4*)(lvl + (size_t)(i0 & ~1u) * 2));
            const float e0x = (i0 & 1u) ? v.z : v.x;
            const float e0y = (i0 & 1u) ? v.w : v.y;
            float e1x, e1y;
            if (i1 == (i0 ^ 1u)) {
                e1x = (i0 & 1u) ? v.x : v.z;
                e1y = (i0 & 1u) ? v.y : v.w;
            } else {
                const float2 e = __ldg((const float2*)(lvl + (size_t)i1 * 2));
                e1x = e.x; e1y = e.y;
            }
            accx = fmaf(wx0, e0x, accx);
            accy = fmaf(wx0, e0y, accy);
            accx = fmaf(wx1, e1x, accx);
            accy = fmaf(wx1, e1y, accy);
        }
        const __half2 h2 = __floats2half2_rn(accx, accy);
        fp[l] = *(const uint32_t*)&h2;
    }

    const unsigned base = ((unsigned)gi >> 5) * 128u + ((unsigned)gi & 31u);
    #pragma unroll
    for (int c = 0; c < 4; c++)
        g_feat[base + (unsigned)c * 32u] =
            make_uint4(fp[4 * c], fp[4 * c + 1], fp[4 * c + 2], fp[4 * c + 3]);
}

// ---- MLP smem layout: 144B stride rows (9 x 16B banks) ----
#define STRIDE   144
#define W0_OFF   0
#define W1_OFF   4608
#define W2_OFF   13824
#define B0_OFF   14848
#define B1_OFF   15104
#define ACT_OFF  15360
#define SMEM_TOTAL 33792

__device__ __forceinline__ uint32_t smem_u32(const void* p) {
    uint32_t a;
    asm("{ .reg .u64 t; cvta.to.shared.u64 t, %1; cvt.u32.u64 %0, t; }"
        : "=r"(a) : "l"(p));
    return a;
}

#define LDM_X4(r0, r1, r2, r3, addr) \
    asm volatile("ldmatrix.sync.aligned.m8n8.x4.shared.b16 {%0,%1,%2,%3}, [%4];" \
        : "=r"(r0), "=r"(r1), "=r"(r2), "=r"(r3) : "r"(addr))

#define LDM_X4_T(r0, r1, r2, r3, addr) \
    asm volatile("ldmatrix.sync.aligned.m8n8.x4.trans.shared.b16 {%0,%1,%2,%3}, [%4];" \
        : "=r"(r0), "=r"(r1), "=r"(r2), "=r"(r3) : "r"(addr))

#define MMA16816(d, a0, a1, a2, a3, b0, b1) \
    asm volatile("mma.sync.aligned.m16n8k16.row.col.f32.f16.f16.f32 " \
        "{%0,%1,%2,%3}, {%4,%5,%6,%7}, {%8,%9}, {%0,%1,%2,%3};" \
        : "+f"((d)[0]), "+f"((d)[1]), "+f"((d)[2]), "+f"((d)[3]) \
        : "r"(a0), "r"(a1), "r"(a2), "r"(a3), "r"(b0), "r"(b1))

// ---------------- Kernel: fused MLP on HMMA, 8 tiles per CTA ----------------
__global__ void __launch_bounds__(128)
mlp_kernel(const float*  __restrict__ w0, const float* __restrict__ b0,
           const float*  __restrict__ w1, const float* __restrict__ b1,
           const float*  __restrict__ w2, const float* __restrict__ b2,
           float* __restrict__ out, int N)
{
    __shared__ __align__(16) uint8_t sm[SMEM_TOTAL];
    const uint32_t sbase = smem_u32(sm);

    const int tid  = threadIdx.x;
    const int wrp  = tid >> 5;
    const int lane = tid & 31;

    // ---- Stage weights ONCE per CTA ----
    for (int i = tid; i < 1024; i += 128) {
        const int k = i >> 5, n2 = i & 31;
        const float2 v = ((const float2*)w0)[i];
        *(__half2*)(sm + W0_OFF + k * STRIDE + n2 * 4) = __floats2half2_rn(v.x, v.y);
    }
    for (int i = tid; i < 2048; i += 128) {
        const int k = i >> 5, n2 = i & 31;
        const float2 v = ((const float2*)w1)[i];
        *(__half2*)(sm + W1_OFF + k * STRIDE + n2 * 4) = __floats2half2_rn(v.x, v.y);
    }
    if (tid < 64) {
        ((float4*)(sm + W2_OFF))[tid] =
            make_float4(w2[tid * 3 + 0], w2[tid * 3 + 1], w2[tid * 3 + 2], 0.0f);
        ((float*)(sm + B0_OFF))[tid] = b0[tid];
        ((float*)(sm + B1_OFF))[tid] = b1[tid];
    }

    const uint32_t actBase = sbase + ACT_OFF + wrp * 32 * STRIDE;
    const uint32_t aRow   = (uint32_t)(lane & 15);
    const uint32_t aColB  = (uint32_t)((lane >> 4) << 4);
    const int      bGrp   = lane >> 3;
    const uint32_t bRow   = (uint32_t)((lane & 7) + ((bGrp & 1) << 3));
    const uint32_t bColB  = (uint32_t)((bGrp >> 1) << 4);
    const int      g      = lane >> 2;
    const int      cp     = (lane & 3) * 2;
    const float    c0 = __ldg(b2 + 0), c1 = __ldg(b2 + 1), c2 = __ldg(b2 + 2);

    for (int t = 0; t < TILES; t++) {
        const int tileIdx = blockIdx.x * TILES + t;
        const int p0 = tileIdx * 128;

        __syncthreads();

        // Coalesced copy: sorted feats for this tile -> act tiles
        {
            const unsigned blk = (unsigned)tileIdx * 512u;
            #pragma unroll
            for (int it = 0; it < 4; it++) {
                const int i = tid + it * 128;
                const int c = i >> 7;
                const int r = i & 127;
                const uint4 v = g_feat[blk + (unsigned)((r >> 5) * 128 + c * 32 + (r & 31))];
                *(uint4*)(sm + ACT_OFF + r * STRIDE + c * 16) = v;
            }
        }
        __syncthreads();

        float acc[2][8][4];

        // Layer 1
        #pragma unroll
        for (int mt = 0; mt < 2; mt++)
            #pragma unroll
            for (int nt = 0; nt < 8; nt++)
                #pragma unroll
                for (int q = 0; q < 4; q++) acc[mt][nt][q] = 0.0f;

        #pragma unroll
        for (int kt = 0; kt < 2; kt++) {
            uint32_t a0[4], a1[4];
            LDM_X4(a0[0], a0[1], a0[2], a0[3],
                   actBase + (0 * 16 + aRow) * STRIDE + aColB + kt * 32);
            LDM_X4(a1[0], a1[1], a1[2], a1[3],
                   actBase + (1 * 16 + aRow) * STRIDE + aColB + kt * 32);
            #pragma unroll
            for (int ntp = 0; ntp < 4; ntp++) {
                uint32_t bf[4];
                LDM_X4_T(bf[0], bf[1], bf[2], bf[3],
                         sbase + W0_OFF + (kt * 16 + bRow) * STRIDE + ntp * 32 + bColB);
                MMA16816(acc[0][2 * ntp + 0], a0[0], a0[1], a0[2], a0[3], bf[0], bf[1]);
                MMA16816(acc[0][2 * ntp + 1], a0[0], a0[1], a0[2], a0[3], bf[2], bf[3]);
                MMA16816(acc[1][2 * ntp + 0], a1[0], a1[1], a1[2], a1[3], bf[0], bf[1]);
                MMA16816(acc[1][2 * ntp + 1], a1[0], a1[1], a1[2], a1[3], bf[2], bf[3]);
            }
        }

        // Epilogue 1
        __syncwarp();
        {
            const float* bb0 = (const float*)(sm + B0_OFF);
            uint8_t* base = sm + ACT_OFF + wrp * 32 * STRIDE;
            #pragma unroll
            for (int mt = 0; mt < 2; mt++)
                #pragma unroll
                for (int nt = 0; nt < 8; nt++) {
                    const int col = nt * 8 + cp;
                    const float bA = bb0[col], bB = bb0[col + 1];
                    const __half2 hA = __floats2half2_rn(
                        fmaxf(acc[mt][nt][0] + bA, 0.0f), fmaxf(acc[mt][nt][1] + bB, 0.0f));
                    const __half2 hB = __floats2half2_rn(
                        fmaxf(acc[mt][nt][2] + bA, 0.0f), fmaxf(acc[mt][nt][3] + bB, 0.0f));
                    *(uint32_t*)(base + (mt * 16 + g)     * STRIDE + col * 2) = *(const uint32_t*)&hA;
                    *(uint32_t*)(base + (mt * 16 + g + 8) * STRIDE + col * 2) = *(const uint32_t*)&hB;
                }
        }
        __syncwarp();

        // Layer 2
        #pragma unroll
        for (int mt = 0; mt < 2; mt++)
            #pragma unroll
            for (int nt = 0; nt < 8; nt++)
                #pragma unroll
                for (int q = 0; q < 4; q++) acc[mt][nt][q] = 0.0f;

        #pragma unroll
        for (int kt = 0; kt < 4; kt++) {
            uint32_t a0[4], a1[4];
            LDM_X4(a0[0], a0[1], a0[2], a0[3],
                   actBase + (0 * 16 + aRow) * STRIDE + aColB + kt * 32);
            LDM_X4(a1[0], a1[1], a1[2], a1[3],
                   actBase + (1 * 16 + aRow) * STRIDE + aColB + kt * 32);
            #pragma unroll
            for (int ntp = 0; ntp < 4; ntp++) {
                uint32_t bf[4];
                LDM_X4_T(bf[0], bf[1], bf[2], bf[3],
                         sbase + W1_OFF + (kt * 16 + bRow) * STRIDE + ntp * 32 + bColB);
                MMA16816(acc[0][2 * ntp + 0], a0[0], a0[1], a0[2], a0[3], bf[0], bf[1]);
                MMA16816(acc[0][2 * ntp + 1], a0[0], a0[1], a0[2], a0[3], bf[2], bf[3]);
                MMA16816(acc[1][2 * ntp + 0], a1[0], a1[1], a1[2], a1[3], bf[0], bf[1]);
                MMA16816(acc[1][2 * ntp + 1], a1[0], a1[1], a1[2], a1[3], bf[2], bf[3]);
            }
        }

        // Epilogue 2 + layer 3 + scatter by original index
        {
            const float*  bb1 = (const float*)(sm + B1_OFF);
            const float4* ww2 = (const float4*)(sm + W2_OFF);
            #pragma unroll
            for (int mt = 0; mt < 2; mt++) {
                float oA0 = 0.0f, oA1 = 0.0f, oA2 = 0.0f;
                float oB0 = 0.0f, oB1 = 0.0f, oB2 = 0.0f;
                #pragma unroll
                for (int nt = 0; nt < 8; nt++) {
                    const int col = nt * 8 + cp;
                    const float4 wA = ww2[col];
                    const float4 wB = ww2[col + 1];
                    const float bA = bb1[col], bB = bb1[col + 1];
                    const float vA0 = fmaxf(acc[mt][nt][0] + bA, 0.0f);
                    const float vA1 = fmaxf(acc[mt][nt][1] + bB, 0.0f);
                    const float vB0 = fmaxf(acc[mt][nt][2] + bA, 0.0f);
                    const float vB1 = fmaxf(acc[mt][nt][3] + bB, 0.0f);
                    oA0 = fmaf(vA0, wA.x, fmaf(vA1, wB.x, oA0));
                    oA1 = fmaf(vA0, wA.y, fmaf(vA1, wB.y, oA1));
                    oA2 = fmaf(vA0, wA.z, fmaf(vA1, wB.z, oA2));
                    oB0 = fmaf(vB0, wA.x, fmaf(vB1, wB.x, oB0));
                    oB1 = fmaf(vB0, wA.y, fmaf(vB1, wB.y, oB1));
                    oB2 = fmaf(vB0, wA.z, fmaf(vB1, wB.z, oB2));
                }
                #pragma unroll
                for (int d = 1; d < 4; d <<= 1) {
                    oA0 += __shfl_xor_sync(0xffffffffu, oA0, d);
                    oA1 += __shfl_xor_sync(0xffffffffu, oA1, d);
                    oA2 += __shfl_xor_sync(0xffffffffu, oA2, d);
                    oB0 += __shfl_xor_sync(0xffffffffu, oB0, d);
                    oB1 += __shfl_xor_sync(0xffffffffu, oB1, d);
                    oB2 += __shfl_xor_sync(0xffffffffu, oB2, d);
                }
                if ((lane & 3) == 0) {
                    const int pA = p0 + wrp * 32 + mt * 16 + g;
                    const int pB = pA + 8;
                    if (pA < N) {
                        const int oi = __float_as_int(g_pts[pA].z);
                        out[oi * 3 + 0] = oA0 + c0;
                        out[oi * 3 + 1] = oA1 + c1;
                        out[oi * 3 + 2] = oA2 + c2;
                    }
                    if (pB < N) {
                        const int oi = __float_as_int(g_pts[pB].z);
                        out[oi * 3 + 0] = oB0 + c0;
                        out[oi * 3 + 1] = oB1 + c1;
                        out[oi * 3 + 2] = oB2 + c2;
                    }
                }
            }
        }
    }
}

extern "C" void kernel_launch(void* const* d_in, const int* in_sizes, int n_in,
                              void* d_out, int out_size)
{
    const float4* x2  = (const float4*)d_in[0];
    const float*  enc = (const float*) d_in[1];
    const float*  w0  = (const float*) d_in[2];
    const float*  b0  = (const float*) d_in[3];
    const float*  w1  = (const float*) d_in[4];
    const float*  b1  = (const float*) d_in[5];
    const float*  w2  = (const float*) d_in[6];
    const float*  b2  = (const float*) d_in[7];
    float* out = (float*)d_out;

    const int N = in_sizes[0] / 2;
    const int nPairs = (N + 1) / 2;
    relayout_kernel<<<HASHMAP_SIZE / 256, 256>>>(enc);
    hist_kernel<<<(nPairs + 255) / 256, 256>>>(x2, N);
    scan_kernel<<<1, 1024>>>();
    scatter_kernel<<<(nPairs + 255) / 256, 256>>>(x2, N);
    encode_kernel<<<(N + 255) / 256, 256>>>(N);
    const int nTiles = (N + 127) / 128;
    mlp_kernel<<<(nTiles + TILES - 1) / TILES, 128>>>(w0, b0, w1, b1, w2, b2, out, N);
}

// round 15
// speedup vs baseline: 1.0098x; 1.0098x over previous
#include <cuda_runtime.h>
#include <cuda_fp16.h>
#include <stdint.h>

// Instant-NGP hash encode + MLP 32->64->64->3.
// R14: R12 kernels (best: 209us) + multi-stream graph fork/join:
//   s0: zero | fork | hist scan scatter | (waits relayout) encode_A | mlp_A | (waits encode_B) mlp_B
//   s2: (waits fork) relayout | (waits encode_A) encode_B
// Streams/events created on the first (uncaptured) call only.

#define HASHMAP_SIZE (1u << 17)
#define HMASK (HASHMAP_SIZE - 1u)
#define TILES 8
#define NBINS 16384            // 128 x 128
#define MAXN  (1 << 20)

__device__ __constant__ float SCALES[16] = {
    16.0f, 24.0f, 36.0f, 54.0f, 81.0f, 121.5f, 182.25f, 273.375f,
    410.0625f, 615.09375f, 922.640625f, 1383.9609375f,
    2075.94140625f, 3113.912109375f, 4670.8681640625f, 7006.30224609375f
};

__device__ __align__(16) float    g_enc2[16 * HASHMAP_SIZE * 2];  // [level][idx][2]
__device__ __align__(16) uint4    g_feat[MAXN * 4];               // sorted-order feats
__device__ __align__(16) float2   g_sx[MAXN];                     // sorted coords
__device__ __align__(16) int      g_sidx[MAXN];                   // sorted -> original
__device__ unsigned g_hist[NBINS];
__device__ unsigned g_binCur[NBINS];

// ---- relayout: [idx][16][2] -> [level][idx][2] (smem transpose) ----
__global__ void __launch_bounds__(256)
relayout_kernel(const float* __restrict__ enc)
{
    __shared__ float s[256 * 33];
    const unsigned base = blockIdx.x * 256;          // idx tile
    for (int i = threadIdx.x; i < 256 * 8; i += 256) {
        const float4 v = ((const float4*)enc)[base * 8 + i];
        const int row = i >> 3, q = i & 7;
        s[row * 33 + q * 4 + 0] = v.x;
        s[row * 33 + q * 4 + 1] = v.y;
        s[row * 33 + q * 4 + 2] = v.z;
        s[row * 33 + q * 4 + 3] = v.w;
    }
    __syncthreads();
    const int i = threadIdx.x;
    #pragma unroll
    for (int l = 0; l < 16; l++) {
        const float2 v = make_float2(s[i * 33 + 2 * l], s[i * 33 + 2 * l + 1]);
        ((float2*)g_enc2)[(size_t)l * HASHMAP_SIZE + base + i] = v;
    }
}

// ---------------- counting sort ----------------
__device__ __forceinline__ int point_bin(float2 p) {
    int bx = (int)(p.x * 128.0f); bx = bx > 127 ? 127 : bx;
    int by = (int)(p.y * 128.0f); by = by > 127 ? 127 : by;
    return by * 128 + bx;
}

__global__ void __launch_bounds__(256)
zero_hist_kernel()
{
    g_hist[blockIdx.x * 256 + threadIdx.x] = 0u;
}

__global__ void __launch_bounds__(256)
hist_kernel(const float2* __restrict__ x, int N)
{
    const int gi = blockIdx.x * 256 + threadIdx.x;
    if (gi >= N) return;
    atomicAdd(&g_hist[point_bin(x[gi])], 1u);
}

// Warp-shuffle exclusive scan over 16384 bins: 1024 threads x 16 bins each.
__global__ void __launch_bounds__(1024)
scan_kernel()
{
    __shared__ unsigned warpTot[32];
    const unsigned t    = threadIdx.x;
    const unsigned lane = t & 31u;
    const unsigned wid  = t >> 5;

    unsigned loc[16];
    unsigned s = 0;
    #pragma unroll
    for (int i = 0; i < 16; i++) { loc[i] = s; s += g_hist[t * 16 + i]; }

    unsigned incl = s;
    #pragma unroll
    for (int d = 1; d < 32; d <<= 1) {
        const unsigned v = __shfl_up_sync(0xffffffffu, incl, d);
        if (lane >= (unsigned)d) incl += v;
    }
    if (lane == 31u) warpTot[wid] = incl;
    __syncthreads();

    if (wid == 0) {
        unsigned v = warpTot[lane];
        unsigned iv = v;
        #pragma unroll
        for (int d = 1; d < 32; d <<= 1) {
            const unsigned u = __shfl_up_sync(0xffffffffu, iv, d);
            if (lane >= (unsigned)d) iv += u;
        }
        warpTot[lane] = iv - v;   // exclusive
    }
    __syncthreads();

    const unsigned base = warpTot[wid] + (incl - s);
    #pragma unroll
    for (int i = 0; i < 16; i++) g_binCur[t * 16 + i] = base + loc[i];
}

__global__ void __launch_bounds__(256)
scatter_kernel(const float2* __restrict__ x, int N)
{
    const int gi = blockIdx.x * 256 + threadIdx.x;
    if (gi >= N) return;
    const float2 p = x[gi];
    const unsigned r = atomicAdd(&g_binCur[point_bin(p)], 1u);
    g_sx[r]   = p;
    g_sidx[r] = gi;
}

// ---------------- Kernel: hash-grid encode (sorted order, [start,end)) ----------------
__global__ void __launch_bounds__(256)
encode_kernel(int start, int end)
{
    const int gi = start + blockIdx.x * 256 + threadIdx.x;
    if (gi >= end) return;
    const float2 xi = g_sx[gi];

    uint32_t fp[16];
    #pragma unroll
    for (int l = 0; l < 16; l++) {
        const float s  = SCALES[l];
        const float px = xi.x * s, py = xi.y * s;
        const float fx = floorf(px), fy = floorf(py);
        const float tx = px - fx,  ty = py - fy;
        const unsigned ix0 = (unsigned)fx, iy0 = (unsigned)fy;
        const float* lvl = g_enc2 + (size_t)l * (HASHMAP_SIZE * 2);

        float accx = 0.0f, accy = 0.0f;
        #pragma unroll
        for (int cy = 0; cy < 2; cy++) {
            const unsigned t  = (iy0 + (unsigned)cy) * 2654435761u;
            const unsigned i0 = (ix0 ^ t) & HMASK;
            const unsigned i1 = ((ix0 + 1u) ^ t) & HMASK;
            const float wy  = cy ? ty : (1.0f - ty);
            const float wx0 = (1.0f - tx) * wy;
            const float wx1 = tx * wy;

            const float4 v = __ldg((const float4*)(lvl + (size_t)(i0 & ~1u) * 2));
            const float e0x = (i0 & 1u) ? v.z : v.x;
            const float e0y = (i0 & 1u) ? v.w : v.y;
            float e1x, e1y;
            if (i1 == (i0 ^ 1u)) {
                e1x = (i0 & 1u) ? v.x : v.z;
                e1y = (i0 & 1u) ? v.y : v.w;
            } else {
                const float2 e = __ldg((const float2*)(lvl + (size_t)i1 * 2));
                e1x = e.x; e1y = e.y;
            }
            accx = fmaf(wx0, e0x, accx);
            accy = fmaf(wx0, e0y, accy);
            accx = fmaf(wx1, e1x, accx);
            accy = fmaf(wx1, e1y, accy);
        }
        const __half2 h2 = __floats2half2_rn(accx, accy);
        fp[l] = *(const uint32_t*)&h2;
    }

    const unsigned base = ((unsigned)gi >> 5) * 128u + ((unsigned)gi & 31u);
    #pragma unroll
    for (int c = 0; c < 4; c++)
        g_feat[base + (unsigned)c * 32u] =
            make_uint4(fp[4 * c], fp[4 * c + 1], fp[4 * c + 2], fp[4 * c + 3]);
}

// ---- MLP smem layout: 144B stride rows (9 x 16B banks) ----
#define STRIDE   144
#define W0_OFF   0
#define W1_OFF   4608
#define W2_OFF   13824
#define B0_OFF   14848
#define B1_OFF   15104
#define ACT_OFF  15360
#define SMEM_TOTAL 33792

__device__ __forceinline__ uint32_t smem_u32(const void* p) {
    uint32_t a;
    asm("{ .reg .u64 t; cvta.to.shared.u64 t, %1; cvt.u32.u64 %0, t; }"
        : "=r"(a) : "l"(p));
    return a;
}

#define LDM_X4(r0, r1, r2, r3, addr) \
    asm volatile("ldmatrix.sync.aligned.m8n8.x4.shared.b16 {%0,%1,%2,%3}, [%4];" \
        : "=r"(r0), "=r"(r1), "=r"(r2), "=r"(r3) : "r"(addr))

#define LDM_X4_T(r0, r1, r2, r3, addr) \
    asm volatile("ldmatrix.sync.aligned.m8n8.x4.trans.shared.b16 {%0,%1,%2,%3}, [%4];" \
        : "=r"(r0), "=r"(r1), "=r"(r2), "=r"(r3) : "r"(addr))

#define MMA16816(d, a0, a1, a2, a3, b0, b1) \
    asm volatile("mma.sync.aligned.m16n8k16.row.col.f32.f16.f16.f32 " \
        "{%0,%1,%2,%3}, {%4,%5,%6,%7}, {%8,%9}, {%0,%1,%2,%3};" \
        : "+f"((d)[0]), "+f"((d)[1]), "+f"((d)[2]), "+f"((d)[3]) \
        : "r"(a0), "r"(a1), "r"(a2), "r"(a3), "r"(b0), "r"(b1))

// ---------------- Kernel: fused MLP on HMMA, 8 tiles per CTA ----------------
__global__ void __launch_bounds__(128)
mlp_kernel(const float*  __restrict__ w0, const float* __restrict__ b0,
           const float*  __restrict__ w1, const float* __restrict__ b1,
           const float*  __restrict__ w2, const float* __restrict__ b2,
           float* __restrict__ out, int N, int tileBase)
{
    __shared__ __align__(16) uint8_t sm[SMEM_TOTAL];
    const uint32_t sbase = smem_u32(sm);

    const int tid  = threadIdx.x;
    const int wrp  = tid >> 5;
    const int lane = tid & 31;

    // ---- Stage weights ONCE per CTA ----
    for (int i = tid; i < 1024; i += 128) {
        const int k = i >> 5, n2 = i & 31;
        const float2 v = ((const float2*)w0)[i];
        *(__half2*)(sm + W0_OFF + k * STRIDE + n2 * 4) = __floats2half2_rn(v.x, v.y);
    }
    for (int i = tid; i < 2048; i += 128) {
        const int k = i >> 5, n2 = i & 31;
        const float2 v = ((const float2*)w1)[i];
        *(__half2*)(sm + W1_OFF + k * STRIDE + n2 * 4) = __floats2half2_rn(v.x, v.y);
    }
    if (tid < 64) {
        ((float4*)(sm + W2_OFF))[tid] =
            make_float4(w2[tid * 3 + 0], w2[tid * 3 + 1], w2[tid * 3 + 2], 0.0f);
        ((float*)(sm + B0_OFF))[tid] = b0[tid];
        ((float*)(sm + B1_OFF))[tid] = b1[tid];
    }

    const uint32_t actBase = sbase + ACT_OFF + wrp * 32 * STRIDE;
    const uint32_t aRow   = (uint32_t)(lane & 15);
    const uint32_t aColB  = (uint32_t)((lane >> 4) << 4);
    const int      bGrp   = lane >> 3;
    const uint32_t bRow   = (uint32_t)((lane & 7) + ((bGrp & 1) << 3));
    const uint32_t bColB  = (uint32_t)((bGrp >> 1) << 4);
    const int      g      = lane >> 2;
    const int      cp     = (lane & 3) * 2;
    const float    c0 = __ldg(b2 + 0), c1 = __ldg(b2 + 1), c2 = __ldg(b2 + 2);

    for (int t = 0; t < TILES; t++) {
        const int tileIdx = tileBase + blockIdx.x * TILES + t;
        const int p0 = tileIdx * 128;
        if (p0 >= N) break;

        __syncthreads();

        // Coalesced copy: sorted feats for this tile -> act tiles
        {
            const unsigned blk = (unsigned)tileIdx * 512u;
            #pragma unroll
            for (int it = 0; it < 4; it++) {
                const int i = tid + it * 128;
                const int c = i >> 7;
                const int r = i & 127;
                const uint4 v = g_feat[blk + (unsigned)((r >> 5) * 128 + c * 32 + (r & 31))];
                *(uint4*)(sm + ACT_OFF + r * STRIDE + c * 16) = v;
            }
        }
        __syncthreads();

        float acc[2][8][4];

        // Layer 1
        #pragma unroll
        for (int mt = 0; mt < 2; mt++)
            #pragma unroll
            for (int nt = 0; nt < 8; nt++)
                #pragma unroll
                for (int q = 0; q < 4; q++) acc[mt][nt][q] = 0.0f;

        #pragma unroll
        for (int kt = 0; kt < 2; kt++) {
            uint32_t a0[4], a1[4];
            LDM_X4(a0[0], a0[1], a0[2], a0[3],
                   actBase + (0 * 16 + aRow) * STRIDE + aColB + kt * 32);
            LDM_X4(a1[0], a1[1], a1[2], a1[3],
                   actBase + (1 * 16 + aRow) * STRIDE + aColB + kt * 32);
            #pragma unroll
            for (int ntp = 0; ntp < 4; ntp++) {
                uint32_t bf[4];
                LDM_X4_T(bf[0], bf[1], bf[2], bf[3],
                         sbase + W0_OFF + (kt * 16 + bRow) * STRIDE + ntp * 32 + bColB);
                MMA16816(acc[0][2 * ntp + 0], a0[0], a0[1], a0[2], a0[3], bf[0], bf[1]);
                MMA16816(acc[0][2 * ntp + 1], a0[0], a0[1], a0[2], a0[3], bf[2], bf[3]);
                MMA16816(acc[1][2 * ntp + 0], a1[0], a1[1], a1[2], a1[3], bf[0], bf[1]);
                MMA16816(acc[1][2 * ntp + 1], a1[0], a1[1], a1[2], a1[3], bf[2], bf[3]);
            }
        }

        // Epilogue 1
        __syncwarp();
        {
            const float* bb0 = (const float*)(sm + B0_OFF);
            uint8_t* base = sm + ACT_OFF + wrp * 32 * STRIDE;
            #pragma unroll
            for (int mt = 0; mt < 2; mt++)
                #pragma unroll
                for (int nt = 0; nt < 8; nt++) {
                    const int col = nt * 8 + cp;
                    const float bA = bb0[col], bB = bb0[col + 1];
                    const __half2 hA = __floats2half2_rn(
                        fmaxf(acc[mt][nt][0] + bA, 0.0f), fmaxf(acc[mt][nt][1] + bB, 0.0f));
                    const __half2 hB = __floats2half2_rn(
                        fmaxf(acc[mt][nt][2] + bA, 0.0f), fmaxf(acc[mt][nt][3] + bB, 0.0f));
                    *(uint32_t*)(base + (mt * 16 + g)     * STRIDE + col * 2) = *(const uint32_t*)&hA;
                    *(uint32_t*)(base + (mt * 16 + g + 8) * STRIDE + col * 2) = *(const uint32_t*)&hB;
                }
        }
        __syncwarp();

        // Layer 2
        #pragma unroll
        for (int mt = 0; mt < 2; mt++)
            #pragma unroll
            for (int nt = 0; nt < 8; nt++)
                #pragma unroll
                for (int q = 0; q < 4; q++) acc[mt][nt][q] = 0.0f;

        #pragma unroll
        for (int kt = 0; kt < 4; kt++) {
            uint32_t a0[4], a1[4];
            LDM_X4(a0[0], a0[1], a0[2], a0[3],
                   actBase + (0 * 16 + aRow) * STRIDE + aColB + kt * 32);
            LDM_X4(a1[0], a1[1], a1[2], a1[3],
                   actBase + (1 * 16 + aRow) * STRIDE + aColB + kt * 32);
            #pragma unroll
            for (int ntp = 0; ntp < 4; ntp++) {
                uint32_t bf[4];
                LDM_X4_T(bf[0], bf[1], bf[2], bf[3],
                         sbase + W1_OFF + (kt * 16 + bRow) * STRIDE + ntp * 32 + bColB);
                MMA16816(acc[0][2 * ntp + 0], a0[0], a0[1], a0[2], a0[3], bf[0], bf[1]);
                MMA16816(acc[0][2 * ntp + 1], a0[0], a0[1], a0[2], a0[3], bf[2], bf[3]);
                MMA16816(acc[1][2 * ntp + 0], a1[0], a1[1], a1[2], a1[3], bf[0], bf[1]);
                MMA16816(acc[1][2 * ntp + 1], a1[0], a1[1], a1[2], a1[3], bf[2], bf[3]);
            }
        }

        // Epilogue 2 + layer 3 + scatter by original index
        {
            const float*  bb1 = (const float*)(sm + B1_OFF);
            const float4* ww2 = (const float4*)(sm + W2_OFF);
            #pragma unroll
            for (int mt = 0; mt < 2; mt++) {
                float oA0 = 0.0f, oA1 = 0.0f, oA2 = 0.0f;
                float oB0 = 0.0f, oB1 = 0.0f, oB2 = 0.0f;
                #pragma unroll
                for (int nt = 0; nt < 8; nt++) {
                    const int col = nt * 8 + cp;
                    const float4 wA = ww2[col];
                    const float4 wB = ww2[col + 1];
                    const float bA = bb1[col], bB = bb1[col + 1];
                    const float vA0 = fmaxf(acc[mt][nt][0] + bA, 0.0f);
                    const float vA1 = fmaxf(acc[mt][nt][1] + bB, 0.0f);
                    const float vB0 = fmaxf(acc[mt][nt][2] + bA, 0.0f);
                    const float vB1 = fmaxf(acc[mt][nt][3] + bB, 0.0f);
                    oA0 = fmaf(vA0, wA.x, fmaf(vA1, wB.x, oA0));
                    oA1 = fmaf(vA0, wA.y, fmaf(vA1, wB.y, oA1));
                    oA2 = fmaf(vA0, wA.z, fmaf(vA1, wB.z, oA2));
                    oB0 = fmaf(vB0, wA.x, fmaf(vB1, wB.x, oB0));
                    oB1 = fmaf(vB0, wA.y, fmaf(vB1, wB.y, oB1));
                    oB2 = fmaf(vB0, wA.z, fmaf(vB1, wB.z, oB2));
                }
                #pragma unroll
                for (int d = 1; d < 4; d <<= 1) {
                    oA0 += __shfl_xor_sync(0xffffffffu, oA0, d);
                    oA1 += __shfl_xor_sync(0xffffffffu, oA1, d);
                    oA2 += __shfl_xor_sync(0xffffffffu, oA2, d);
                    oB0 += __shfl_xor_sync(0xffffffffu, oB0, d);
                    oB1 += __shfl_xor_sync(0xffffffffu, oB1, d);
                    oB2 += __shfl_xor_sync(0xffffffffu, oB2, d);
                }
                if ((lane & 3) == 0) {
                    const int pA = p0 + wrp * 32 + mt * 16 + g;
                    const int pB = pA + 8;
                    if (pA < N) {
                        const int oi = g_sidx[pA];
                        out[oi * 3 + 0] = oA0 + c0;
                        out[oi * 3 + 1] = oA1 + c1;
                        out[oi * 3 + 2] = oA2 + c2;
                    }
                    if (pB < N) {
                        const int oi = g_sidx[pB];
                        out[oi * 3 + 0] = oB0 + c0;
                        out[oi * 3 + 1] = oB1 + c1;
                        out[oi * 3 + 2] = oB2 + c2;
                    }
                }
            }
        }
    }
}

// ---------------- host: multi-stream fork/join pipeline ----------------
static cudaStream_t g_s2 = nullptr;
static cudaEvent_t  g_evStart = nullptr, g_evRel = nullptr, g_evA = nullptr, g_evB = nullptr;

extern "C" void kernel_launch(void* const* d_in, const int* in_sizes, int n_in,
                              void* d_out, int out_size)
{
    const float2* x   = (const float2*)d_in[0];
    const float*  enc = (const float*) d_in[1];
    const float*  w0  = (const float*) d_in[2];
    const float*  b0  = (const float*) d_in[3];
    const float*  w1  = (const float*) d_in[4];
    const float*  b1  = (const float*) d_in[5];
    const float*  w2  = (const float*) d_in[6];
    const float*  b2  = (const float*) d_in[7];
    float* out = (float*)d_out;

    // One-time resource creation (first call runs outside graph capture).
    if (g_s2 == nullptr) {
        cudaStreamCreateWithFlags(&g_s2, cudaStreamNonBlocking);
        cudaEventCreateWithFlags(&g_evStart, cudaEventDisableTiming);
        cudaEventCreateWithFlags(&g_evRel,   cudaEventDisableTiming);
        cudaEventCreateWithFlags(&g_evA,     cudaEventDisableTiming);
        cudaEventCreateWithFlags(&g_evB,     cudaEventDisableTiming);
    }

    const int N = in_sizes[0] / 2;
    const int nTiles = (N + 127) / 128;
    // Half split aligned to TILES*128 = 1024 points
    int halfN = ((N / 2) + 1023) & ~1023;
    if (halfN > N) halfN = N;
    const int tilesA = halfN / 128;
    const int tilesB = nTiles - tilesA;

    // s0: zero hist, then fork
    zero_hist_kernel<<<NBINS / 256, 256>>>();
    cudaEventRecord(g_evStart, 0);

    // s2: relayout (independent of the sort chain)
    cudaStreamWaitEvent(g_s2, g_evStart, 0);
    relayout_kernel<<<HASHMAP_SIZE / 256, 256, 0, g_s2>>>(enc);
    cudaEventRecord(g_evRel, g_s2);

    // s0: sort chain
    hist_kernel<<<(N + 255) / 256, 256>>>(x, N);
    scan_kernel<<<1, 1024>>>();
    scatter_kernel<<<(N + 255) / 256, 256>>>(x, N);

    // s0: encode half A (needs relayout + scatter)
    cudaStreamWaitEvent(0, g_evRel, 0);
    encode_kernel<<<(halfN + 255) / 256, 256>>>(0, halfN);
    cudaEventRecord(g_evA, 0);

    // s2: encode half B overlapped with mlp half A
    cudaStreamWaitEvent(g_s2, g_evA, 0);
    if (N > halfN)
        encode_kernel<<<(N - halfN + 255) / 256, 256, 0, g_s2>>>(halfN, N);
    cudaEventRecord(g_evB, g_s2);

    // s0: mlp half A
    if (tilesA > 0)
        mlp_kernel<<<(tilesA + TILES - 1) / TILES, 128>>>(w0, b0, w1, b1, w2, b2, out, N, 0);

    // s0: join, then mlp half B
    cudaStreamWaitEvent(0, g_evB, 0);
    if (tilesB > 0)
        mlp_kernel<<<(tilesB + TILES - 1) / TILES, 128>>>(w0, b0, w1, b1, w2, b2, out, N, tilesA);
}

// round 16
// speedup vs baseline: 1.0606x; 1.0503x over previous
#include <cuda_runtime.h>
#include <cuda_fp16.h>
#include <stdint.h>

// Instant-NGP hash encode + MLP 32->64->64->3.
// R16: single-stream R12 pipeline with (a) uint4-vectorized scan (the old one
// was single-SM LSU-throughput-bound at 16us on 16K scalar LDG/STG), and
// (b) hist zeroing folded into scan's read loop (graph-replay state reuse) ->
// zero_hist kernel removed.

#define HASHMAP_SIZE (1u << 17)
#define HMASK (HASHMAP_SIZE - 1u)
#define TILES 8
#define NBINS 16384            // 128 x 128
#define MAXN  (1 << 20)

__device__ __constant__ float SCALES[16] = {
    16.0f, 24.0f, 36.0f, 54.0f, 81.0f, 121.5f, 182.25f, 273.375f,
    410.0625f, 615.09375f, 922.640625f, 1383.9609375f,
    2075.94140625f, 3113.912109375f, 4670.8681640625f, 7006.30224609375f
};

__device__ __align__(16) float    g_enc2[16 * HASHMAP_SIZE * 2];  // [level][idx][2]
__device__ __align__(16) uint4    g_feat[MAXN * 4];               // sorted-order feats
__device__ __align__(16) float2   g_sx[MAXN];                     // sorted coords
__device__ __align__(16) int      g_sidx[MAXN];                   // sorted -> original
__device__ __align__(16) unsigned g_hist[NBINS];                  // zero-init; scan resets
__device__ __align__(16) unsigned g_binCur[NBINS];

// ---- relayout: [idx][16][2] -> [level][idx][2] (smem transpose) ----
__global__ void __launch_bounds__(256)
relayout_kernel(const float* __restrict__ enc)
{
    __shared__ float s[256 * 33];
    const unsigned base = blockIdx.x * 256;          // idx tile
    for (int i = threadIdx.x; i < 256 * 8; i += 256) {
        const float4 v = ((const float4*)enc)[base * 8 + i];
        const int row = i >> 3, q = i & 7;
        s[row * 33 + q * 4 + 0] = v.x;
        s[row * 33 + q * 4 + 1] = v.y;
        s[row * 33 + q * 4 + 2] = v.z;
        s[row * 33 + q * 4 + 3] = v.w;
    }
    __syncthreads();
    const int i = threadIdx.x;
    #pragma unroll
    for (int l = 0; l < 16; l++) {
        const float2 v = make_float2(s[i * 33 + 2 * l], s[i * 33 + 2 * l + 1]);
        ((float2*)g_enc2)[(size_t)l * HASHMAP_SIZE + base + i] = v;
    }
}

// ---------------- counting sort ----------------
__device__ __forceinline__ int point_bin(float2 p) {
    int bx = (int)(p.x * 128.0f); bx = bx > 127 ? 127 : bx;
    int by = (int)(p.y * 128.0f); by = by > 127 ? 127 : by;
    return by * 128 + bx;
}

__global__ void __launch_bounds__(256)
hist_kernel(const float2* __restrict__ x, int N)
{
    const int gi = blockIdx.x * 256 + threadIdx.x;
    if (gi >= N) return;
    atomicAdd(&g_hist[point_bin(x[gi])], 1u);
}

// Vectorized warp-shuffle exclusive scan over 16384 bins.
// 1024 threads x 16 bins each, uint4 loads/stores; also resets g_hist to 0
// for the next graph replay (first run relies on static zero-init).
__global__ void __launch_bounds__(1024)
scan_kernel()
{
    __shared__ unsigned warpTot[32];
    const unsigned t    = threadIdx.x;
    const unsigned lane = t & 31u;
    const unsigned wid  = t >> 5;

    uint4 h[4];
    #pragma unroll
    for (int i = 0; i < 4; i++) h[i] = ((const uint4*)g_hist)[t * 4 + i];
    #pragma unroll
    for (int i = 0; i < 4; i++)
        ((uint4*)g_hist)[t * 4 + i] = make_uint4(0u, 0u, 0u, 0u);

    unsigned v[16] = { h[0].x, h[0].y, h[0].z, h[0].w,
                       h[1].x, h[1].y, h[1].z, h[1].w,
                       h[2].x, h[2].y, h[2].z, h[2].w,
                       h[3].x, h[3].y, h[3].z, h[3].w };
    unsigned loc[16];
    unsigned s = 0;
    #pragma unroll
    for (int i = 0; i < 16; i++) { loc[i] = s; s += v[i]; }

    unsigned incl = s;
    #pragma unroll
    for (int d = 1; d < 32; d <<= 1) {
        const unsigned u = __shfl_up_sync(0xffffffffu, incl, d);
        if (lane >= (unsigned)d) incl += u;
    }
    if (lane == 31u) warpTot[wid] = incl;
    __syncthreads();

    if (wid == 0) {
        unsigned w = warpTot[lane];
        unsigned iw = w;
        #pragma unroll
        for (int d = 1; d < 32; d <<= 1) {
            const unsigned u = __shfl_up_sync(0xffffffffu, iw, d);
            if (lane >= (unsigned)d) iw += u;
        }
        warpTot[lane] = iw - w;   // exclusive
    }
    __syncthreads();

    const unsigned base = warpTot[wid] + (incl - s);
    #pragma unroll
    for (int i = 0; i < 4; i++) {
        const uint4 o = make_uint4(base + loc[4 * i + 0], base + loc[4 * i + 1],
                                   base + loc[4 * i + 2], base + loc[4 * i + 3]);
        ((uint4*)g_binCur)[t * 4 + i] = o;
    }
}

__global__ void __launch_bounds__(256)
scatter_kernel(const float2* __restrict__ x, int N)
{
    const int gi = blockIdx.x * 256 + threadIdx.x;
    if (gi >= N) return;
    const float2 p = x[gi];
    const unsigned r = atomicAdd(&g_binCur[point_bin(p)], 1u);
    g_sx[r]   = p;
    g_sidx[r] = gi;
}

// ---------------- Kernel: hash-grid encode (sorted order) ----------------
__global__ void __launch_bounds__(256)
encode_kernel(int N)
{
    const int gi = blockIdx.x * 256 + threadIdx.x;
    if (gi >= N) return;
    const float2 xi = g_sx[gi];

    uint32_t fp[16];
    #pragma unroll
    for (int l = 0; l < 16; l++) {
        const float s  = SCALES[l];
        const float px = xi.x * s, py = xi.y * s;
        const float fx = floorf(px), fy = floorf(py);
        const float tx = px - fx,  ty = py - fy;
        const unsigned ix0 = (unsigned)fx, iy0 = (unsigned)fy;
        const float* lvl = g_enc2 + (size_t)l * (HASHMAP_SIZE * 2);

        float accx = 0.0f, accy = 0.0f;
        #pragma unroll
        for (int cy = 0; cy < 2; cy++) {
            const unsigned t  = (iy0 + (unsigned)cy) * 2654435761u;
            const unsigned i0 = (ix0 ^ t) & HMASK;
            const unsigned i1 = ((ix0 + 1u) ^ t) & HMASK;
            const float wy  = cy ? ty : (1.0f - ty);
            const float wx0 = (1.0f - tx) * wy;
            const float wx1 = tx * wy;

            const float4 v = __ldg((const float4*)(lvl + (size_t)(i0 & ~1u) * 2));
            const float e0x = (i0 & 1u) ? v.z : v.x;
            const float e0y = (i0 & 1u) ? v.w : v.y;
            float e1x, e1y;
            if (i1 == (i0 ^ 1u)) {
                e1x = (i0 & 1u) ? v.x : v.z;
                e1y = (i0 & 1u) ? v.y : v.w;
            } else {
                const float2 e = __ldg((const float2*)(lvl + (size_t)i1 * 2));
                e1x = e.x; e1y = e.y;
            }
            accx = fmaf(wx0, e0x, accx);
            accy = fmaf(wx0, e0y, accy);
            accx = fmaf(wx1, e1x, accx);
            accy = fmaf(wx1, e1y, accy);
        }
        const __half2 h2 = __floats2half2_rn(accx, accy);
        fp[l] = *(const uint32_t*)&h2;
    }

    const unsigned base = ((unsigned)gi >> 5) * 128u + ((unsigned)gi & 31u);
    #pragma unroll
    for (int c = 0; c < 4; c++)
        g_feat[base + (unsigned)c * 32u] =
            make_uint4(fp[4 * c], fp[4 * c + 1], fp[4 * c + 2], fp[4 * c + 3]);
}

// ---- MLP smem layout: 144B stride rows (9 x 16B banks) ----
#define STRIDE   144
#define W0_OFF   0
#define W1_OFF   4608
#define W2_OFF   13824
#define B0_OFF   14848
#define B1_OFF   15104
#define ACT_OFF  15360
#define SMEM_TOTAL 33792

__device__ __forceinline__ uint32_t smem_u32(const void* p) {
    uint32_t a;
    asm("{ .reg .u64 t; cvta.to.shared.u64 t, %1; cvt.u32.u64 %0, t; }"
        : "=r"(a) : "l"(p));
    return a;
}

#define LDM_X4(r0, r1, r2, r3, addr) \
    asm volatile("ldmatrix.sync.aligned.m8n8.x4.shared.b16 {%0,%1,%2,%3}, [%4];" \
        : "=r"(r0), "=r"(r1), "=r"(r2), "=r"(r3) : "r"(addr))

#define LDM_X4_T(r0, r1, r2, r3, addr) \
    asm volatile("ldmatrix.sync.aligned.m8n8.x4.trans.shared.b16 {%0,%1,%2,%3}, [%4];" \
        : "=r"(r0), "=r"(r1), "=r"(r2), "=r"(r3) : "r"(addr))

#define MMA16816(d, a0, a1, a2, a3, b0, b1) \
    asm volatile("mma.sync.aligned.m16n8k16.row.col.f32.f16.f16.f32 " \
        "{%0,%1,%2,%3}, {%4,%5,%6,%7}, {%8,%9}, {%0,%1,%2,%3};" \
        : "+f"((d)[0]), "+f"((d)[1]), "+f"((d)[2]), "+f"((d)[3]) \
        : "r"(a0), "r"(a1), "r"(a2), "r"(a3), "r"(b0), "r"(b1))

// ---------------- Kernel: fused MLP on HMMA, 8 tiles per CTA ----------------
__global__ void __launch_bounds__(128)
mlp_kernel(const float*  __restrict__ w0, const float* __restrict__ b0,
           const float*  __restrict__ w1, const float* __restrict__ b1,
           const float*  __restrict__ w2, const float* __restrict__ b2,
           float* __restrict__ out, int N)
{
    __shared__ __align__(16) uint8_t sm[SMEM_TOTAL];
    const uint32_t sbase = smem_u32(sm);

    const int tid  = threadIdx.x;
    const int wrp  = tid >> 5;
    const int lane = tid & 31;

    // ---- Stage weights ONCE per CTA ----
    for (int i = tid; i < 1024; i += 128) {
        const int k = i >> 5, n2 = i & 31;
        const float2 v = ((const float2*)w0)[i];
        *(__half2*)(sm + W0_OFF + k * STRIDE + n2 * 4) = __floats2half2_rn(v.x, v.y);
    }
    for (int i = tid; i < 2048; i += 128) {
        const int k = i >> 5, n2 = i & 31;
        const float2 v = ((const float2*)w1)[i];
        *(__half2*)(sm + W1_OFF + k * STRIDE + n2 * 4) = __floats2half2_rn(v.x, v.y);
    }
    if (tid < 64) {
        ((float4*)(sm + W2_OFF))[tid] =
            make_float4(w2[tid * 3 + 0], w2[tid * 3 + 1], w2[tid * 3 + 2], 0.0f);
        ((float*)(sm + B0_OFF))[tid] = b0[tid];
        ((float*)(sm + B1_OFF))[tid] = b1[tid];
    }

    const uint32_t actBase = sbase + ACT_OFF + wrp * 32 * STRIDE;
    const uint32_t aRow   = (uint32_t)(lane & 15);
    const uint32_t aColB  = (uint32_t)((lane >> 4) << 4);
    const int      bGrp   = lane >> 3;
    const uint32_t bRow   = (uint32_t)((lane & 7) + ((bGrp & 1) << 3));
    const uint32_t bColB  = (uint32_t)((bGrp >> 1) << 4);
    const int      g      = lane >> 2;
    const int      cp     = (lane & 3) * 2;
    const float    c0 = __ldg(b2 + 0), c1 = __ldg(b2 + 1), c2 = __ldg(b2 + 2);

    for (int t = 0; t < TILES; t++) {
        const int tileIdx = blockIdx.x * TILES + t;
        const int p0 = tileIdx * 128;

        __syncthreads();

        // Coalesced copy: sorted feats for this tile -> act tiles
        {
            const unsigned blk = (unsigned)tileIdx * 512u;
            #pragma unroll
            for (int it = 0; it < 4; it++) {
                const int i = tid + it * 128;
                const int c = i >> 7;
                const int r = i & 127;
                const uint4 v = g_feat[blk + (unsigned)((r >> 5) * 128 + c * 32 + (r & 31))];
                *(uint4*)(sm + ACT_OFF + r * STRIDE + c * 16) = v;
            }
        }
        __syncthreads();

        float acc[2][8][4];

        // Layer 1
        #pragma unroll
        for (int mt = 0; mt < 2; mt++)
            #pragma unroll
            for (int nt = 0; nt < 8; nt++)
                #pragma unroll
                for (int q = 0; q < 4; q++) acc[mt][nt][q] = 0.0f;

        #pragma unroll
        for (int kt = 0; kt < 2; kt++) {
            uint32_t a0[4], a1[4];
            LDM_X4(a0[0], a0[1], a0[2], a0[3],
                   actBase + (0 * 16 + aRow) * STRIDE + aColB + kt * 32);
            LDM_X4(a1[0], a1[1], a1[2], a1[3],
                   actBase + (1 * 16 + aRow) * STRIDE + aColB + kt * 32);
            #pragma unroll
            for (int ntp = 0; ntp < 4; ntp++) {
                uint32_t bf[4];
                LDM_X4_T(bf[0], bf[1], bf[2], bf[3],
                         sbase + W0_OFF + (kt * 16 + bRow) * STRIDE + ntp * 32 + bColB);
                MMA16816(acc[0][2 * ntp + 0], a0[0], a0[1], a0[2], a0[3], bf[0], bf[1]);
                MMA16816(acc[0][2 * ntp + 1], a0[0], a0[1], a0[2], a0[3], bf[2], bf[3]);
                MMA16816(acc[1][2 * ntp + 0], a1[0], a1[1], a1[2], a1[3], bf[0], bf[1]);
                MMA16816(acc[1][2 * ntp + 1], a1[0], a1[1], a1[2], a1[3], bf[2], bf[3]);
            }
        }

        // Epilogue 1
        __syncwarp();
        {
            const float* bb0 = (const float*)(sm + B0_OFF);
            uint8_t* base = sm + ACT_OFF + wrp * 32 * STRIDE;
            #pragma unroll
            for (int mt = 0; mt < 2; mt++)
                #pragma unroll
                for (int nt = 0; nt < 8; nt++) {
                    const int col = nt * 8 + cp;
                    const float bA = bb0[col], bB = bb0[col + 1];
                    const __half2 hA = __floats2half2_rn(
                        fmaxf(acc[mt][nt][0] + bA, 0.0f), fmaxf(acc[mt][nt][1] + bB, 0.0f));
                    const __half2 hB = __floats2half2_rn(
                        fmaxf(acc[mt][nt][2] + bA, 0.0f), fmaxf(acc[mt][nt][3] + bB, 0.0f));
                    *(uint32_t*)(base + (mt * 16 + g)     * STRIDE + col * 2) = *(const uint32_t*)&hA;
                    *(uint32_t*)(base + (mt * 16 + g + 8) * STRIDE + col * 2) = *(const uint32_t*)&hB;
                }
        }
        __syncwarp();

        // Layer 2
        #pragma unroll
        for (int mt = 0; mt < 2; mt++)
            #pragma unroll
            for (int nt = 0; nt < 8; nt++)
                #pragma unroll
                for (int q = 0; q < 4; q++) acc[mt][nt][q] = 0.0f;

        #pragma unroll
        for (int kt = 0; kt < 4; kt++) {
            uint32_t a0[4], a1[4];
            LDM_X4(a0[0], a0[1], a0[2], a0[3],
                   actBase + (0 * 16 + aRow) * STRIDE + aColB + kt * 32);
            LDM_X4(a1[0], a1[1], a1[2], a1[3],
                   actBase + (1 * 16 + aRow) * STRIDE + aColB + kt * 32);
            #pragma unroll
            for (int ntp = 0; ntp < 4; ntp++) {
                uint32_t bf[4];
                LDM_X4_T(bf[0], bf[1], bf[2], bf[3],
                         sbase + W1_OFF + (kt * 16 + bRow) * STRIDE + ntp * 32 + bColB);
                MMA16816(acc[0][2 * ntp + 0], a0[0], a0[1], a0[2], a0[3], bf[0], bf[1]);
                MMA16816(acc[0][2 * ntp + 1], a0[0], a0[1], a0[2], a0[3], bf[2], bf[3]);
                MMA16816(acc[1][2 * ntp + 0], a1[0], a1[1], a1[2], a1[3], bf[0], bf[1]);
                MMA16816(acc[1][2 * ntp + 1], a1[0], a1[1], a1[2], a1[3], bf[2], bf[3]);
            }
        }

        // Epilogue 2 + layer 3 + scatter by original index
        {
            const float*  bb1 = (const float*)(sm + B1_OFF);
            const float4* ww2 = (const float4*)(sm + W2_OFF);
            #pragma unroll
            for (int mt = 0; mt < 2; mt++) {
                float oA0 = 0.0f, oA1 = 0.0f, oA2 = 0.0f;
                float oB0 = 0.0f, oB1 = 0.0f, oB2 = 0.0f;
                #pragma unroll
                for (int nt = 0; nt < 8; nt++) {
                    const int col = nt * 8 + cp;
                    const float4 wA = ww2[col];
                    const float4 wB = ww2[col + 1];
                    const float bA = bb1[col], bB = bb1[col + 1];
                    const float vA0 = fmaxf(acc[mt][nt][0] + bA, 0.0f);
                    const float vA1 = fmaxf(acc[mt][nt][1] + bB, 0.0f);
                    const float vB0 = fmaxf(acc[mt][nt][2] + bA, 0.0f);
                    const float vB1 = fmaxf(acc[mt][nt][3] + bB, 0.0f);
                    oA0 = fmaf(vA0, wA.x, fmaf(vA1, wB.x, oA0));
                    oA1 = fmaf(vA0, wA.y, fmaf(vA1, wB.y, oA1));
                    oA2 = fmaf(vA0, wA.z, fmaf(vA1, wB.z, oA2));
                    oB0 = fmaf(vB0, wA.x, fmaf(vB1, wB.x, oB0));
                    oB1 = fmaf(vB0, wA.y, fmaf(vB1, wB.y, oB1));
                    oB2 = fmaf(vB0, wA.z, fmaf(vB1, wB.z, oB2));
                }
                #pragma unroll
                for (int d = 1; d < 4; d <<= 1) {
                    oA0 += __shfl_xor_sync(0xffffffffu, oA0, d);
                    oA1 += __shfl_xor_sync(0xffffffffu, oA1, d);
                    oA2 += __shfl_xor_sync(0xffffffffu, oA2, d);
                    oB0 += __shfl_xor_sync(0xffffffffu, oB0, d);
                    oB1 += __shfl_xor_sync(0xffffffffu, oB1, d);
                    oB2 += __shfl_xor_sync(0xffffffffu, oB2, d);
                }
                if ((lane & 3) == 0) {
                    const int pA = p0 + wrp * 32 + mt * 16 + g;
                    const int pB = pA + 8;
                    if (pA < N) {
                        const int oi = g_sidx[pA];
                        out[oi * 3 + 0] = oA0 + c0;
                        out[oi * 3 + 1] = oA1 + c1;
                        out[oi * 3 + 2] = oA2 + c2;
                    }
                    if (pB < N) {
                        const int oi = g_sidx[pB];
                        out[oi * 3 + 0] = oB0 + c0;
                        out[oi * 3 + 1] = oB1 + c1;
                        out[oi * 3 + 2] = oB2 + c2;
                    }
                }
            }
        }
    }
}

extern "C" void kernel_launch(void* const* d_in, const int* in_sizes, int n_in,
                              void* d_out, int out_size)
{
    const float2* x   = (const float2*)d_in[0];
    const float*  enc = (const float*) d_in[1];
    const float*  w0  = (const float*) d_in[2];
    const float*  b0  = (const float*) d_in[3];
    const float*  w1  = (const float*) d_in[4];
    const float*  b1  = (const float*) d_in[5];
    const float*  w2  = (const float*) d_in[6];
    const float*  b2  = (const float*) d_in[7];
    float* out = (float*)d_out;

    const int N = in_sizes[0] / 2;
    relayout_kernel<<<HASHMAP_SIZE / 256, 256>>>(enc);
    hist_kernel<<<(N + 255) / 256, 256>>>(x, N);
    scan_kernel<<<1, 1024>>>();
    scatter_kernel<<<(N + 255) / 256, 256>>>(x, N);
    encode_kernel<<<(N + 255) / 256, 256>>>(N);
    const int nTiles = (N + 127) / 128;
    mlp_kernel<<<(nTiles + TILES - 1) / TILES, 128>>>(w0, b0, w1, b1, w2, b2, out, N);
}

// round 17
// speedup vs baseline: 1.1764x; 1.1092x over previous
#include <cuda_runtime.h>
#include <cuda_fp16.h>
#include <stdint.h>

// Instant-NGP hash encode + MLP 32->64->64->3.
// R16: encode fused INTO the MLP tile loop (feats written straight to the smem
// act tile; g_feat 64MB scratch + its 128MB round-trip + one launch removed).
// Sort chain (hist/scan/scatter) and relayout unchanged from R15.

#define HASHMAP_SIZE (1u << 17)
#define HMASK (HASHMAP_SIZE - 1u)
#define TILES 8
#define NBINS 16384            // 128 x 128
#define MAXN  (1 << 20)

__device__ __constant__ float SCALES[16] = {
    16.0f, 24.0f, 36.0f, 54.0f, 81.0f, 121.5f, 182.25f, 273.375f,
    410.0625f, 615.09375f, 922.640625f, 1383.9609375f,
    2075.94140625f, 3113.912109375f, 4670.8681640625f, 7006.30224609375f
};

__device__ __align__(16) float    g_enc2[16 * HASHMAP_SIZE * 2];  // [level][idx][2]
__device__ __align__(16) float2   g_sx[MAXN];                     // sorted coords
__device__ __align__(16) int      g_sidx[MAXN];                   // sorted -> original
__device__ __align__(16) unsigned g_hist[NBINS];                  // zero-init; scan resets
__device__ __align__(16) unsigned g_binCur[NBINS];

// ---- relayout: [idx][16][2] -> [level][idx][2] (smem transpose) ----
__global__ void __launch_bounds__(256)
relayout_kernel(const float* __restrict__ enc)
{
    __shared__ float s[256 * 33];
    const unsigned base = blockIdx.x * 256;          // idx tile
    for (int i = threadIdx.x; i < 256 * 8; i += 256) {
        const float4 v = ((const float4*)enc)[base * 8 + i];
        const int row = i >> 3, q = i & 7;
        s[row * 33 + q * 4 + 0] = v.x;
        s[row * 33 + q * 4 + 1] = v.y;
        s[row * 33 + q * 4 + 2] = v.z;
        s[row * 33 + q * 4 + 3] = v.w;
    }
    __syncthreads();
    const int i = threadIdx.x;
    #pragma unroll
    for (int l = 0; l < 16; l++) {
        const float2 v = make_float2(s[i * 33 + 2 * l], s[i * 33 + 2 * l + 1]);
        ((float2*)g_enc2)[(size_t)l * HASHMAP_SIZE + base + i] = v;
    }
}

// ---------------- counting sort ----------------
__device__ __forceinline__ int point_bin(float2 p) {
    int bx = (int)(p.x * 128.0f); bx = bx > 127 ? 127 : bx;
    int by = (int)(p.y * 128.0f); by = by > 127 ? 127 : by;
    return by * 128 + bx;
}

__global__ void __launch_bounds__(256)
hist_kernel(const float2* __restrict__ x, int N)
{
    const int gi = blockIdx.x * 256 + threadIdx.x;
    if (gi >= N) return;
    atomicAdd(&g_hist[point_bin(x[gi])], 1u);
}

// Vectorized warp-shuffle exclusive scan over 16384 bins; resets g_hist.
__global__ void __launch_bounds__(1024)
scan_kernel()
{
    __shared__ unsigned warpTot[32];
    const unsigned t    = threadIdx.x;
    const unsigned lane = t & 31u;
    const unsigned wid  = t >> 5;

    uint4 h[4];
    #pragma unroll
    for (int i = 0; i < 4; i++) h[i] = ((const uint4*)g_hist)[t * 4 + i];
    #pragma unroll
    for (int i = 0; i < 4; i++)
        ((uint4*)g_hist)[t * 4 + i] = make_uint4(0u, 0u, 0u, 0u);

    unsigned v[16] = { h[0].x, h[0].y, h[0].z, h[0].w,
                       h[1].x, h[1].y, h[1].z, h[1].w,
                       h[2].x, h[2].y, h[2].z, h[2].w,
                       h[3].x, h[3].y, h[3].z, h[3].w };
    unsigned loc[16];
    unsigned s = 0;
    #pragma unroll
    for (int i = 0; i < 16; i++) { loc[i] = s; s += v[i]; }

    unsigned incl = s;
    #pragma unroll
    for (int d = 1; d < 32; d <<= 1) {
        const unsigned u = __shfl_up_sync(0xffffffffu, incl, d);
        if (lane >= (unsigned)d) incl += u;
    }
    if (lane == 31u) warpTot[wid] = incl;
    __syncthreads();

    if (wid == 0) {
        unsigned w = warpTot[lane];
        unsigned iw = w;
        #pragma unroll
        for (int d = 1; d < 32; d <<= 1) {
            const unsigned u = __shfl_up_sync(0xffffffffu, iw, d);
            if (lane >= (unsigned)d) iw += u;
        }
        warpTot[lane] = iw - w;   // exclusive
    }
    __syncthreads();

    const unsigned base = warpTot[wid] + (incl - s);
    #pragma unroll
    for (int i = 0; i < 4; i++) {
        const uint4 o = make_uint4(base + loc[4 * i + 0], base + loc[4 * i + 1],
                                   base + loc[4 * i + 2], base + loc[4 * i + 3]);
        ((uint4*)g_binCur)[t * 4 + i] = o;
    }
}

__global__ void __launch_bounds__(256)
scatter_kernel(const float2* __restrict__ x, int N)
{
    const int gi = blockIdx.x * 256 + threadIdx.x;
    if (gi >= N) return;
    const float2 p = x[gi];
    const unsigned r = atomicAdd(&g_binCur[point_bin(p)], 1u);
    g_sx[r]   = p;
    g_sidx[r] = gi;
}

// ---- MLP smem layout: 144B stride rows (9 x 16B banks) ----
#define STRIDE   144
#define W0_OFF   0
#define W1_OFF   4608
#define W2_OFF   13824
#define B0_OFF   14848
#define B1_OFF   15104
#define ACT_OFF  15360
#define SMEM_TOTAL 33792

__device__ __forceinline__ uint32_t smem_u32(const void* p) {
    uint32_t a;
    asm("{ .reg .u64 t; cvta.to.shared.u64 t, %1; cvt.u32.u64 %0, t; }"
        : "=r"(a) : "l"(p));
    return a;
}

#define LDM_X4(r0, r1, r2, r3, addr) \
    asm volatile("ldmatrix.sync.aligned.m8n8.x4.shared.b16 {%0,%1,%2,%3}, [%4];" \
        : "=r"(r0), "=r"(r1), "=r"(r2), "=r"(r3) : "r"(addr))

#define LDM_X4_T(r0, r1, r2, r3, addr) \
    asm volatile("ldmatrix.sync.aligned.m8n8.x4.trans.shared.b16 {%0,%1,%2,%3}, [%4];" \
        : "=r"(r0), "=r"(r1), "=r"(r2), "=r"(r3) : "r"(addr))

#define MMA16816(d, a0, a1, a2, a3, b0, b1) \
    asm volatile("mma.sync.aligned.m16n8k16.row.col.f32.f16.f16.f32 " \
        "{%0,%1,%2,%3}, {%4,%5,%6,%7}, {%8,%9}, {%0,%1,%2,%3};" \
        : "+f"((d)[0]), "+f"((d)[1]), "+f"((d)[2]), "+f"((d)[3]) \
        : "r"(a0), "r"(a1), "r"(a2), "r"(a3), "r"(b0), "r"(b1))

// ------- Fused kernel: per tile, hash-encode -> smem act -> HMMA MLP -------
__global__ void __launch_bounds__(128)
fused_kernel(const float*  __restrict__ w0, const float* __restrict__ b0,
             const float*  __restrict__ w1, const float* __restrict__ b1,
             const float*  __restrict__ w2, const float* __restrict__ b2,
             float* __restrict__ out, int N)
{
    __shared__ __align__(16) uint8_t sm[SMEM_TOTAL];
    const uint32_t sbase = smem_u32(sm);

    const int tid  = threadIdx.x;
    const int wrp  = tid >> 5;
    const int lane = tid & 31;

    // ---- Stage weights ONCE per CTA ----
    for (int i = tid; i < 1024; i += 128) {
        const int k = i >> 5, n2 = i & 31;
        const float2 v = ((const float2*)w0)[i];
        *(__half2*)(sm + W0_OFF + k * STRIDE + n2 * 4) = __floats2half2_rn(v.x, v.y);
    }
    for (int i = tid; i < 2048; i += 128) {
        const int k = i >> 5, n2 = i & 31;
        const float2 v = ((const float2*)w1)[i];
        *(__half2*)(sm + W1_OFF + k * STRIDE + n2 * 4) = __floats2half2_rn(v.x, v.y);
    }
    if (tid < 64) {
        ((float4*)(sm + W2_OFF))[tid] =
            make_float4(w2[tid * 3 + 0], w2[tid * 3 + 1], w2[tid * 3 + 2], 0.0f);
        ((float*)(sm + B0_OFF))[tid] = b0[tid];
        ((float*)(sm + B1_OFF))[tid] = b1[tid];
    }

    const uint32_t actBase = sbase + ACT_OFF + wrp * 32 * STRIDE;
    const uint32_t aRow   = (uint32_t)(lane & 15);
    const uint32_t aColB  = (uint32_t)((lane >> 4) << 4);
    const int      bGrp   = lane >> 3;
    const uint32_t bRow   = (uint32_t)((lane & 7) + ((bGrp & 1) << 3));
    const uint32_t bColB  = (uint32_t)((bGrp >> 1) << 4);
    const int      g      = lane >> 2;
    const int      cp     = (lane & 3) * 2;
    const float    c0 = __ldg(b2 + 0), c1 = __ldg(b2 + 1), c2 = __ldg(b2 + 2);

    for (int t = 0; t < TILES; t++) {
        const int tileIdx = blockIdx.x * TILES + t;
        const int p0 = tileIdx * 128;

        __syncthreads();   // previous tile's act fully consumed (or weights staged)

        // ---- Hash-grid encode: this thread's point -> act row (fp16) ----
        {
            const int gp = p0 + tid;
            const float2 xi = (gp < N) ? g_sx[gp] : make_float2(0.0f, 0.0f);

            uint32_t fp[16];
            #pragma unroll
            for (int l = 0; l < 16; l++) {
                const float s  = SCALES[l];
                const float px = xi.x * s, py = xi.y * s;
                const float fx = floorf(px), fy = floorf(py);
                const float tx = px - fx,  ty = py - fy;
                const unsigned ix0 = (unsigned)fx, iy0 = (unsigned)fy;
                const float* lvl = g_enc2 + (size_t)l * (HASHMAP_SIZE * 2);

                float accx = 0.0f, accy = 0.0f;
                #pragma unroll
                for (int cy = 0; cy < 2; cy++) {
                    const unsigned tt = (iy0 + (unsigned)cy) * 2654435761u;
                    const unsigned i0 = (ix0 ^ tt) & HMASK;
                    const unsigned i1 = ((ix0 + 1u) ^ tt) & HMASK;
                    const float wy  = cy ? ty : (1.0f - ty);
                    const float wx0 = (1.0f - tx) * wy;
                    const float wx1 = tx * wy;

                    const float4 v = __ldg((const float4*)(lvl + (size_t)(i0 & ~1u) * 2));
                    const float e0x = (i0 & 1u) ? v.z : v.x;
                    const float e0y = (i0 & 1u) ? v.w : v.y;
                    float e1x, e1y;
                    if (i1 == (i0 ^ 1u)) {
                        e1x = (i0 & 1u) ? v.x : v.z;
                        e1y = (i0 & 1u) ? v.y : v.w;
                    } else {
                        const float2 e = __ldg((const float2*)(lvl + (size_t)i1 * 2));
                        e1x = e.x; e1y = e.y;
                    }
                    accx = fmaf(wx0, e0x, accx);
                    accy = fmaf(wx0, e0y, accy);
                    accx = fmaf(wx1, e1x, accx);
                    accy = fmaf(wx1, e1y, accy);
                }
                const __half2 h2 = __floats2half2_rn(accx, accy);
                fp[l] = *(const uint32_t*)&h2;
            }

            uint8_t* row = sm + ACT_OFF + tid * STRIDE;
            #pragma unroll
            for (int c = 0; c < 4; c++)
                *(uint4*)(row + c * 16) =
                    make_uint4(fp[4 * c], fp[4 * c + 1], fp[4 * c + 2], fp[4 * c + 3]);
        }
        __syncthreads();

        float acc[2][8][4];

        // ---------------- Layer 1: [32x32] @ [32x64] ----------------
        #pragma unroll
        for (int mt = 0; mt < 2; mt++)
            #pragma unroll
            for (int nt = 0; nt < 8; nt++)
                #pragma unroll
                for (int q = 0; q < 4; q++) acc[mt][nt][q] = 0.0f;

        #pragma unroll
        for (int kt = 0; kt < 2; kt++) {
            uint32_t a0[4], a1[4];
            LDM_X4(a0[0], a0[1], a0[2], a0[3],
                   actBase + (0 * 16 + aRow) * STRIDE + aColB + kt * 32);
            LDM_X4(a1[0], a1[1], a1[2], a1[3],
                   actBase + (1 * 16 + aRow) * STRIDE + aColB + kt * 32);
            #pragma unroll
            for (int ntp = 0; ntp < 4; ntp++) {
                uint32_t bf[4];
                LDM_X4_T(bf[0], bf[1], bf[2], bf[3],
                         sbase + W0_OFF + (kt * 16 + bRow) * STRIDE + ntp * 32 + bColB);
                MMA16816(acc[0][2 * ntp + 0], a0[0], a0[1], a0[2], a0[3], bf[0], bf[1]);
                MMA16816(acc[0][2 * ntp + 1], a0[0], a0[1], a0[2], a0[3], bf[2], bf[3]);
                MMA16816(acc[1][2 * ntp + 0], a1[0], a1[1], a1[2], a1[3], bf[0], bf[1]);
                MMA16816(acc[1][2 * ntp + 1], a1[0], a1[1], a1[2], a1[3], bf[2], bf[3]);
            }
        }

        // Epilogue 1: relu(acc + b0) -> fp16 -> act tile
        __syncwarp();
        {
            const float* bb0 = (const float*)(sm + B0_OFF);
            uint8_t* base = sm + ACT_OFF + wrp * 32 * STRIDE;
            #pragma unroll
            for (int mt = 0; mt < 2; mt++)
                #pragma unroll
                for (int nt = 0; nt < 8; nt++) {
                    const int col = nt * 8 + cp;
                    const float bA = bb0[col], bB = bb0[col + 1];
                    const __half2 hA = __floats2half2_rn(
                        fmaxf(acc[mt][nt][0] + bA, 0.0f), fmaxf(acc[mt][nt][1] + bB, 0.0f));
                    const __half2 hB = __floats2half2_rn(
                        fmaxf(acc[mt][nt][2] + bA, 0.0f), fmaxf(acc[mt][nt][3] + bB, 0.0f));
                    *(uint32_t*)(base + (mt * 16 + g)     * STRIDE + col * 2) = *(const uint32_t*)&hA;
                    *(uint32_t*)(base + (mt * 16 + g + 8) * STRIDE + col * 2) = *(const uint32_t*)&hB;
                }
        }
        __syncwarp();

        // ---------------- Layer 2: [32x64] @ [64x64] ----------------
        #pragma unroll
        for (int mt = 0; mt < 2; mt++)
            #pragma unroll
            for (int nt = 0; nt < 8; nt++)
                #pragma unroll
                for (int q = 0; q < 4; q++) acc[mt][nt][q] = 0.0f;

        #pragma unroll
        for (int kt = 0; kt < 4; kt++) {
            uint32_t a0[4], a1[4];
            LDM_X4(a0[0], a0[1], a0[2], a0[3],
                   actBase + (0 * 16 + aRow) * STRIDE + aColB + kt * 32);
            LDM_X4(a1[0], a1[1], a1[2], a1[3],
                   actBase + (1 * 16 + aRow) * STRIDE + aColB + kt * 32);
            #pragma unroll
            for (int ntp = 0; ntp < 4; ntp++) {
                uint32_t bf[4];
                LDM_X4_T(bf[0], bf[1], bf[2], bf[3],
                         sbase + W1_OFF + (kt * 16 + bRow) * STRIDE + ntp * 32 + bColB);
                MMA16816(acc[0][2 * ntp + 0], a0[0], a0[1], a0[2], a0[3], bf[0], bf[1]);
                MMA16816(acc[0][2 * ntp + 1], a0[0], a0[1], a0[2], a0[3], bf[2], bf[3]);
                MMA16816(acc[1][2 * ntp + 0], a1[0], a1[1], a1[2], a1[3], bf[0], bf[1]);
                MMA16816(acc[1][2 * ntp + 1], a1[0], a1[1], a1[2], a1[3], bf[2], bf[3]);
            }
        }

        // Epilogue 2 + layer 3 + scatter by original index
        {
            const float*  bb1 = (const float*)(sm + B1_OFF);
            const float4* ww2 = (const float4*)(sm + W2_OFF);
            #pragma unroll
            for (int mt = 0; mt < 2; mt++) {
                float oA0 = 0.0f, oA1 = 0.0f, oA2 = 0.0f;
                float oB0 = 0.0f, oB1 = 0.0f, oB2 = 0.0f;
                #pragma unroll
                for (int nt = 0; nt < 8; nt++) {
                    const int col = nt * 8 + cp;
                    const float4 wA = ww2[col];
                    const float4 wB = ww2[col + 1];
                    const float bA = bb1[col], bB = bb1[col + 1];
                    const float vA0 = fmaxf(acc[mt][nt][0] + bA, 0.0f);
                    const float vA1 = fmaxf(acc[mt][nt][1] + bB, 0.0f);
                    const float vB0 = fmaxf(acc[mt][nt][2] + bA, 0.0f);
                    const float vB1 = fmaxf(acc[mt][nt][3] + bB, 0.0f);
                    oA0 = fmaf(vA0, wA.x, fmaf(vA1, wB.x, oA0));
                    oA1 = fmaf(vA0, wA.y, fmaf(vA1, wB.y, oA1));
                    oA2 = fmaf(vA0, wA.z, fmaf(vA1, wB.z, oA2));
                    oB0 = fmaf(vB0, wA.x, fmaf(vB1, wB.x, oB0));
                    oB1 = fmaf(vB0, wA.y, fmaf(vB1, wB.y, oB1));
                    oB2 = fmaf(vB0, wA.z, fmaf(vB1, wB.z, oB2));
                }
                #pragma unroll
                for (int d = 1; d < 4; d <<= 1) {
                    oA0 += __shfl_xor_sync(0xffffffffu, oA0, d);
                    oA1 += __shfl_xor_sync(0xffffffffu, oA1, d);
                    oA2 += __shfl_xor_sync(0xffffffffu, oA2, d);
                    oB0 += __shfl_xor_sync(0xffffffffu, oB0, d);
                    oB1 += __shfl_xor_sync(0xffffffffu, oB1, d);
                    oB2 += __shfl_xor_sync(0xffffffffu, oB2, d);
                }
                if ((lane & 3) == 0) {
                    const int pA = p0 + wrp * 32 + mt * 16 + g;
                    const int pB = pA + 8;
                    if (pA < N) {
                        const int oi = g_sidx[pA];
                        out[oi * 3 + 0] = oA0 + c0;
                        out[oi * 3 + 1] = oA1 + c1;
                        out[oi * 3 + 2] = oA2 + c2;
                    }
                    if (pB < N) {
                        const int oi = g_sidx[pB];
                        out[oi * 3 + 0] = oB0 + c0;
                        out[oi * 3 + 1] = oB1 + c1;
                        out[oi * 3 + 2] = oB2 + c2;
                    }
                }
            }
        }
    }
}

extern "C" void kernel_launch(void* const* d_in, const int* in_sizes, int n_in,
                              void* d_out, int out_size)
{
    const float2* x   = (const float2*)d_in[0];
    const float*  enc = (const float*) d_in[1];
    const float*  w0  = (const float*) d_in[2];
    const float*  b0  = (const float*) d_in[3];
    const float*  w1  = (const float*) d_in[4];
    const float*  b1  = (const float*) d_in[5];
    const float*  w2  = (const float*) d_in[6];
    const float*  b2  = (const float*) d_in[7];
    float* out = (float*)d_out;

    const int N = in_sizes[0] / 2;
    relayout_kernel<<<HASHMAP_SIZE / 256, 256>>>(enc);
    hist_kernel<<<(N + 255) / 256, 256>>>(x, N);
    scan_kernel<<<1, 1024>>>();
    scatter_kernel<<<(N + 255) / 256, 256>>>(x, N);
    const int nTiles = (N + 127) / 128;
    fused_kernel<<<(nTiles + TILES - 1) / TILES, 128>>>(w0, b0, w1, b1, w2, b2, out, N);
}